// round 1
// baseline (speedup 1.0000x reference)
#include <cuda_runtime.h>
#include <cstdint>

#define TILE 32
#define HDIM 512
#define NTHREADS 512

__device__ float g_sf[2][4][HDIM];

__device__ __forceinline__ void fma2(unsigned long long &d, unsigned long long a, unsigned long long b){
    asm("fma.rn.f32x2 %0, %1, %2, %0;" : "+l"(d) : "l"(a), "l"(b));
}
__device__ __forceinline__ float unpack_sum(unsigned long long v){
    float lo, hi;
    asm("mov.b64 {%0,%1}, %2;" : "=f"(lo), "=f"(hi) : "l"(v));
    return lo + hi;
}

// sf[f][b][:] = tanh(code[b] @ cond_w^T + cond_b)
__global__ void sf_kernel(const float* __restrict__ code,
                          const float* __restrict__ cw1, const float* __restrict__ cb1,
                          const float* __restrict__ cw2, const float* __restrict__ cb2){
    int b = blockIdx.x, f = blockIdx.y, t = threadIdx.x;
    const float* cw = f ? cw2 : cw1;
    const float* cb = f ? cb2 : cb1;
    const float4* c4 = reinterpret_cast<const float4*>(code + b*HDIM);
    const float4* w4 = reinterpret_cast<const float4*>(cw + t*HDIM);
    float s = 0.f;
    #pragma unroll 4
    for (int i = 0; i < HDIM/4; i++){
        float4 a = c4[i], w = w4[i];
        s = fmaf(a.x, w.x, fmaf(a.y, w.y, fmaf(a.z, w.z, fmaf(a.w, w.w, s))));
    }
    g_sf[f][b][t] = tanhf(s + cb[t]);
}

__global__ __launch_bounds__(NTHREADS, 1)
void deform_kernel(const float* __restrict__ x_in, float* __restrict__ x_out,
    const float* __restrict__ W1a, const float* __restrict__ b1a,
    const float* __restrict__ W2a, const float* __restrict__ b2a,
    const float* __restrict__ W3a, const float* __restrict__ b3a,
    const float* __restrict__ W4a, const float* __restrict__ b4a,
    const float* __restrict__ W1b, const float* __restrict__ b1b,
    const float* __restrict__ W2b, const float* __restrict__ b2b,
    const float* __restrict__ W3b, const float* __restrict__ b3b,
    const float* __restrict__ W4b, const float* __restrict__ b4b)
{
    extern __shared__ __align__(16) float smem[];
    float (*h)[HDIM] = reinterpret_cast<float(*)[HDIM]>(smem);   // TILE x 512 activation tile

    __shared__ float p0[TILE][3];    // integrated position
    __shared__ float pe[TILE][3];    // evaluation point for current k
    __shared__ float ksum[TILE][3];  // k1 + 2k2 + 2k3 + k4 accumulator
    __shared__ float kc[TILE][3];    // current dyn() output

    const int t = threadIdx.x;
    const int base = blockIdx.x * TILE;   // global row base in [0, 16384)
    const int b = base >> 12;             // batch index (4096 rows per batch)

    if (t < TILE*3){
        int r = t/3, j = t - r*3;
        float v = x_in[(base + r)*3 + j];
        p0[r][j] = v; pe[r][j] = v;
    }
    __syncthreads();

    const float dt = 0.05f;  // TIME / N_STEPS = 0.2 / 4

    for (int f = 0; f < 2; ++f){
        const float* W1 = f ? W1b : W1a;
        const float* B1 = f ? b1b : b1a;
        const float* W2 = f ? W2b : W2a;
        const float* B2 = f ? b2b : b2a;
        const float* W3 = f ? W3b : W3a;
        const float* B3 = f ? b3b : b3a;
        const float* W4 = f ? W4b : W4a;
        const float* B4 = f ? b4b : b4a;

        // per-column constants for this block (thread t owns hidden column t)
        const float w1x = W1[t*3+0], w1y = W1[t*3+1], w1z = W1[t*3+2];
        const float bb1 = B1[t], bb2 = B2[t], bb3 = B3[t];
        const float sfv = g_sf[f][b][t];
        const ulonglong2* __restrict__ W2r = reinterpret_cast<const ulonglong2*>(W2 + t*HDIM);
        const ulonglong2* __restrict__ W3r = reinterpret_cast<const ulonglong2*>(W3 + t*HDIM);

        for (int step = 0; step < 4; ++step){
            for (int s = 0; s < 4; ++s){
                // ---- stage 1: h = relu(pe @ W1^T + b1) * sf  (each thread writes its column)
                #pragma unroll
                for (int r = 0; r < TILE; ++r){
                    float v = fmaf(pe[r][0], w1x, fmaf(pe[r][1], w1y, fmaf(pe[r][2], w1z, bb1)));
                    h[r][t] = fmaxf(v, 0.f) * sfv;
                }
                __syncthreads();

                // ---- stages 2,3: h = relu(h @ W^T + b) + h   (packed f32x2 mainloop)
                for (int g = 0; g < 2; ++g){
                    const ulonglong2* __restrict__ Wr = g ? W3r : W2r;
                    const float bb = g ? bb3 : bb2;
                    unsigned long long acc[TILE];
                    #pragma unroll
                    for (int r = 0; r < TILE; ++r) acc[r] = 0ull;

                    #pragma unroll 2
                    for (int k4 = 0; k4 < HDIM/4; ++k4){
                        ulonglong2 w = Wr[k4];  // W[t][4k..4k+3] from L2
                        #pragma unroll
                        for (int r = 0; r < TILE; ++r){
                            ulonglong2 hv = *reinterpret_cast<const ulonglong2*>(&h[r][k4*4]); // broadcast LDS.128
                            fma2(acc[r], w.x, hv.x);
                            fma2(acc[r], w.y, hv.y);
                        }
                    }
                    float newv[TILE];
                    #pragma unroll
                    for (int r = 0; r < TILE; ++r){
                        float sacc = unpack_sum(acc[r]) + bb;
                        newv[r] = fmaxf(sacc, 0.f) + h[r][t];   // residual
                    }
                    __syncthreads();   // everyone done reading old h
                    #pragma unroll
                    for (int r = 0; r < TILE; ++r) h[r][t] = newv[r];
                    __syncthreads();
                }

                // ---- stage 4: kc = tanh(h @ W4^T + b4); one warp per 2 rows, lane-split over k
                {
                    const int wid = t >> 5, lane = t & 31;
                    float a[2][3];
                    #pragma unroll
                    for (int rr = 0; rr < 2; ++rr)
                        #pragma unroll
                        for (int j = 0; j < 3; ++j) a[rr][j] = 0.f;

                    #pragma unroll 4
                    for (int i = 0; i < HDIM/32; ++i){
                        int k = lane + i*32;
                        float w0 = W4[0*HDIM + k], w1 = W4[1*HDIM + k], w2 = W4[2*HDIM + k];
                        #pragma unroll
                        for (int rr = 0; rr < 2; ++rr){
                            float hv = h[wid*2 + rr][k];
                            a[rr][0] = fmaf(hv, w0, a[rr][0]);
                            a[rr][1] = fmaf(hv, w1, a[rr][1]);
                            a[rr][2] = fmaf(hv, w2, a[rr][2]);
                        }
                    }
                    #pragma unroll
                    for (int rr = 0; rr < 2; ++rr)
                        #pragma unroll
                        for (int j = 0; j < 3; ++j){
                            float v = a[rr][j];
                            #pragma unroll
                            for (int off = 16; off > 0; off >>= 1)
                                v += __shfl_xor_sync(0xffffffffu, v, off);
                            if (lane == 0) kc[wid*2 + rr][j] = tanhf(v + B4[j]);
                        }
                }
                __syncthreads();

                // ---- RK4 state update
                if (t < TILE*3){
                    int r = t/3, j = t - r*3;
                    float k = kc[r][j];
                    if (s == 0){ ksum[r][j] = k;            pe[r][j] = fmaf(0.5f*dt, k, p0[r][j]); }
                    else if (s == 1){ ksum[r][j] += 2.f*k;  pe[r][j] = fmaf(0.5f*dt, k, p0[r][j]); }
                    else if (s == 2){ ksum[r][j] += 2.f*k;  pe[r][j] = fmaf(dt, k, p0[r][j]); }
                    else { float p = fmaf(dt/6.f, ksum[r][j] + k, p0[r][j]); p0[r][j] = p; pe[r][j] = p; }
                }
                __syncthreads();
            }
        }
    }

    if (t < TILE*3){
        int r = t/3, j = t - r*3;
        x_out[(base + r)*3 + j] = p0[r][j];
    }
}

extern "C" void kernel_launch(void* const* d_in, const int* in_sizes, int n_in,
                              void* d_out, int out_size)
{
    const float* code   = (const float*)d_in[0];
    const float* x      = (const float*)d_in[1];
    const float* f1_l1w = (const float*)d_in[2];
    const float* f1_l1b = (const float*)d_in[3];
    const float* f1_l2w = (const float*)d_in[4];
    const float* f1_l2b = (const float*)d_in[5];
    const float* f1_l3w = (const float*)d_in[6];
    const float* f1_l3b = (const float*)d_in[7];
    const float* f1_l4w = (const float*)d_in[8];
    const float* f1_l4b = (const float*)d_in[9];
    const float* f1_cw  = (const float*)d_in[10];
    const float* f1_cb  = (const float*)d_in[11];
    const float* f2_l1w = (const float*)d_in[12];
    const float* f2_l1b = (const float*)d_in[13];
    const float* f2_l2w = (const float*)d_in[14];
    const float* f2_l2b = (const float*)d_in[15];
    const float* f2_l3w = (const float*)d_in[16];
    const float* f2_l3b = (const float*)d_in[17];
    const float* f2_l4w = (const float*)d_in[18];
    const float* f2_l4b = (const float*)d_in[19];
    const float* f2_cw  = (const float*)d_in[20];
    const float* f2_cb  = (const float*)d_in[21];
    float* out = (float*)d_out;

    static int smem_set = 0;
    (void)smem_set;
    cudaFuncSetAttribute(deform_kernel, cudaFuncAttributeMaxDynamicSharedMemorySize,
                         TILE * HDIM * (int)sizeof(float));

    sf_kernel<<<dim3(4, 2), HDIM>>>(code, f1_cw, f1_cb, f2_cw, f2_cb);

    const int n_blocks = (4 * 4096) / TILE;  // 512
    deform_kernel<<<n_blocks, NTHREADS, TILE * HDIM * sizeof(float)>>>(
        x, out,
        f1_l1w, f1_l1b, f1_l2w, f1_l2b, f1_l3w, f1_l3b, f1_l4w, f1_l4b,
        f2_l1w, f2_l1b, f2_l2w, f2_l2b, f2_l3w, f2_l3b, f2_l4w, f2_l4b);
}

// round 3
// speedup vs baseline: 1.1528x; 1.1528x over previous
#include <cuda_runtime.h>
#include <cstdint>

#define TILE 16          // rows per CTA
#define HDIM 512
#define NTHREADS 256     // each thread owns hidden cols t and t+256

__device__ float g_sf[2][4][HDIM];

__device__ __forceinline__ void fma2(unsigned long long &d, unsigned long long a, unsigned long long b){
    asm("fma.rn.f32x2 %0, %1, %2, %0;" : "+l"(d) : "l"(a), "l"(b));
}
__device__ __forceinline__ float unpack_sum(unsigned long long v){
    float lo, hi;
    asm("mov.b64 {%0,%1}, %2;" : "=f"(lo), "=f"(hi) : "l"(v));
    return lo + hi;
}

// sf[f][b][:] = tanh(code[b] @ cond_w^T + cond_b)
__global__ void sf_kernel(const float* __restrict__ code,
                          const float* __restrict__ cw1, const float* __restrict__ cb1,
                          const float* __restrict__ cw2, const float* __restrict__ cb2){
    int b = blockIdx.x, f = blockIdx.y, t = threadIdx.x;
    const float* cw = f ? cw2 : cw1;
    const float* cb = f ? cb2 : cb1;
    const float4* c4 = reinterpret_cast<const float4*>(code + b*HDIM);
    const float4* w4 = reinterpret_cast<const float4*>(cw + t*HDIM);
    float s = 0.f;
    #pragma unroll 4
    for (int i = 0; i < HDIM/4; i++){
        float4 a = c4[i], w = w4[i];
        s = fmaf(a.x, w.x, fmaf(a.y, w.y, fmaf(a.z, w.z, fmaf(a.w, w.w, s))));
    }
    g_sf[f][b][t] = tanhf(s + cb[t]);
}

__global__ __launch_bounds__(NTHREADS, 2)
void deform_kernel(const float* __restrict__ x_in, float* __restrict__ x_out,
    const float* __restrict__ W1a, const float* __restrict__ b1a,
    const float* __restrict__ W2a, const float* __restrict__ b2a,
    const float* __restrict__ W3a, const float* __restrict__ b3a,
    const float* __restrict__ W4a, const float* __restrict__ b4a,
    const float* __restrict__ W1b, const float* __restrict__ b1b,
    const float* __restrict__ W2b, const float* __restrict__ b2b,
    const float* __restrict__ W3b, const float* __restrict__ b3b,
    const float* __restrict__ W4b, const float* __restrict__ b4b)
{
    extern __shared__ __align__(16) float smem[];
    float (*h)[HDIM] = reinterpret_cast<float(*)[HDIM]>(smem);   // TILE x 512 activation tile

    __shared__ float p0[TILE][3];    // integrated position
    __shared__ float pe[TILE][3];    // evaluation point for current k
    __shared__ float ksum[TILE][3];  // k1 + 2k2 + 2k3 + k4 accumulator
    __shared__ float kc[TILE][3];    // current dyn() output

    const int t = threadIdx.x;
    const int c0 = t, c1 = t + 256;       // hidden columns owned by this thread
    const int base = blockIdx.x * TILE;   // global row base in [0, 16384)
    const int b = base >> 12;             // batch index (4096 rows per batch)

    if (t < TILE*3){
        int r = t/3, j = t - r*3;
        float v = x_in[(base + r)*3 + j];
        p0[r][j] = v; pe[r][j] = v;
    }
    __syncthreads();

    const float dt = 0.05f;  // TIME / N_STEPS

    for (int f = 0; f < 2; ++f){
        const float* W1 = f ? W1b : W1a;
        const float* B1 = f ? b1b : b1a;
        const float* W2 = f ? W2b : W2a;
        const float* B2 = f ? b2b : b2a;
        const float* W3 = f ? W3b : W3a;
        const float* B3 = f ? b3b : b3a;
        const float* W4 = f ? W4b : W4a;
        const float* B4 = f ? b4b : b4a;

        // per-column constants (this thread owns columns c0 and c1)
        const float w1x0 = W1[c0*3+0], w1y0 = W1[c0*3+1], w1z0 = W1[c0*3+2];
        const float w1x1 = W1[c1*3+0], w1y1 = W1[c1*3+1], w1z1 = W1[c1*3+2];
        const float bb1_0 = B1[c0], bb1_1 = B1[c1];
        const float bb2_0 = B2[c0], bb2_1 = B2[c1];
        const float bb3_0 = B3[c0], bb3_1 = B3[c1];
        const float sf0 = g_sf[f][b][c0], sf1 = g_sf[f][b][c1];
        const ulonglong2* __restrict__ W2r0 = reinterpret_cast<const ulonglong2*>(W2 + c0*HDIM);
        const ulonglong2* __restrict__ W2r1 = reinterpret_cast<const ulonglong2*>(W2 + c1*HDIM);
        const ulonglong2* __restrict__ W3r0 = reinterpret_cast<const ulonglong2*>(W3 + c0*HDIM);
        const ulonglong2* __restrict__ W3r1 = reinterpret_cast<const ulonglong2*>(W3 + c1*HDIM);

        for (int step = 0; step < 4; ++step){
            for (int s = 0; s < 4; ++s){
                // ---- stage 1: h = relu(pe @ W1^T + b1) * sf
                #pragma unroll
                for (int r = 0; r < TILE; ++r){
                    float px = pe[r][0], py = pe[r][1], pz = pe[r][2];
                    float v0 = fmaf(px, w1x0, fmaf(py, w1y0, fmaf(pz, w1z0, bb1_0)));
                    float v1 = fmaf(px, w1x1, fmaf(py, w1y1, fmaf(pz, w1z1, bb1_1)));
                    h[r][c0] = fmaxf(v0, 0.f) * sf0;
                    h[r][c1] = fmaxf(v1, 0.f) * sf1;
                }
                __syncthreads();

                // ---- stages 2,3: h = relu(h @ W^T + b) + h   (f32x2 mainloop, 2 cols/thread)
                #pragma unroll 1
                for (int g = 0; g < 2; ++g){
                    const ulonglong2* __restrict__ Wr0 = g ? W3r0 : W2r0;
                    const ulonglong2* __restrict__ Wr1 = g ? W3r1 : W2r1;
                    const float bbc0 = g ? bb3_0 : bb2_0;
                    const float bbc1 = g ? bb3_1 : bb2_1;

                    unsigned long long acc0[TILE], acc1[TILE];
                    #pragma unroll
                    for (int r = 0; r < TILE; ++r){ acc0[r] = 0ull; acc1[r] = 0ull; }

                    // register double-buffered W stream (2 rows, 16B each per k4)
                    ulonglong2 w0 = Wr0[0], w1 = Wr1[0];
                    #pragma unroll 2
                    for (int k4 = 0; k4 < HDIM/4; ++k4){
                        ulonglong2 nw0, nw1;
                        if (k4 + 1 < HDIM/4){ nw0 = Wr0[k4+1]; nw1 = Wr1[k4+1]; }
                        #pragma unroll
                        for (int r = 0; r < TILE; ++r){
                            ulonglong2 hv = *reinterpret_cast<const ulonglong2*>(&h[r][k4*4]); // broadcast LDS.128
                            fma2(acc0[r], w0.x, hv.x);
                            fma2(acc0[r], w0.y, hv.y);
                            fma2(acc1[r], w1.x, hv.x);
                            fma2(acc1[r], w1.y, hv.y);
                        }
                        w0 = nw0; w1 = nw1;
                    }

                    float nv0[TILE], nv1[TILE];
                    #pragma unroll
                    for (int r = 0; r < TILE; ++r){
                        nv0[r] = fmaxf(unpack_sum(acc0[r]) + bbc0, 0.f) + h[r][c0];
                        nv1[r] = fmaxf(unpack_sum(acc1[r]) + bbc1, 0.f) + h[r][c1];
                    }
                    __syncthreads();   // all reads of old h complete
                    #pragma unroll
                    for (int r = 0; r < TILE; ++r){ h[r][c0] = nv0[r]; h[r][c1] = nv1[r]; }
                    __syncthreads();
                }

                // ---- stage 4: kc = tanh(h @ W4^T + b4); 8 warps, 2 rows per warp
                {
                    const int wid = t >> 5, lane = t & 31;
                    float a00=0.f, a01=0.f, a02=0.f, a10=0.f, a11=0.f, a12=0.f;
                    #pragma unroll 4
                    for (int i = 0; i < HDIM/32; ++i){
                        int k = lane + i*32;
                        float w0 = W4[0*HDIM + k], w1 = W4[1*HDIM + k], w2 = W4[2*HDIM + k];
                        float hv0 = h[wid*2 + 0][k];
                        float hv1 = h[wid*2 + 1][k];
                        a00 = fmaf(hv0, w0, a00); a01 = fmaf(hv0, w1, a01); a02 = fmaf(hv0, w2, a02);
                        a10 = fmaf(hv1, w0, a10); a11 = fmaf(hv1, w1, a11); a12 = fmaf(hv1, w2, a12);
                    }
                    float av[6] = {a00, a01, a02, a10, a11, a12};
                    #pragma unroll
                    for (int j = 0; j < 6; ++j){
                        float v = av[j];
                        #pragma unroll
                        for (int off = 16; off > 0; off >>= 1)
                            v += __shfl_xor_sync(0xffffffffu, v, off);
                        if (lane == 0) kc[wid*2 + (j/3)][j%3] = tanhf(v + B4[j%3]);
                    }
                }
                __syncthreads();

                // ---- RK4 state update
                if (t < TILE*3){
                    int r = t/3, j = t - r*3;
                    float k = kc[r][j];
                    if (s == 0){ ksum[r][j] = k;            pe[r][j] = fmaf(0.5f*dt, k, p0[r][j]); }
                    else if (s == 1){ ksum[r][j] += 2.f*k;  pe[r][j] = fmaf(0.5f*dt, k, p0[r][j]); }
                    else if (s == 2){ ksum[r][j] += 2.f*k;  pe[r][j] = fmaf(dt, k, p0[r][j]); }
                    else { float p = fmaf(dt/6.f, ksum[r][j] + k, p0[r][j]); p0[r][j] = p; pe[r][j] = p; }
                }
                __syncthreads();
            }
        }
    }

    if (t < TILE*3){
        int r = t/3, j = t - r*3;
        x_out[(base + r)*3 + j] = p0[r][j];
    }
}

extern "C" void kernel_launch(void* const* d_in, const int* in_sizes, int n_in,
                              void* d_out, int out_size)
{
    const float* code   = (const float*)d_in[0];
    const float* x      = (const float*)d_in[1];
    const float* f1_l1w = (const float*)d_in[2];
    const float* f1_l1b = (const float*)d_in[3];
    const float* f1_l2w = (const float*)d_in[4];
    const float* f1_l2b = (const float*)d_in[5];
    const float* f1_l3w = (const float*)d_in[6];
    const float* f1_l3b = (const float*)d_in[7];
    const float* f1_l4w = (const float*)d_in[8];
    const float* f1_l4b = (const float*)d_in[9];
    const float* f1_cw  = (const float*)d_in[10];
    const float* f1_cb  = (const float*)d_in[11];
    const float* f2_l1w = (const float*)d_in[12];
    const float* f2_l1b = (const float*)d_in[13];
    const float* f2_l2w = (const float*)d_in[14];
    const float* f2_l2b = (const float*)d_in[15];
    const float* f2_l3w = (const float*)d_in[16];
    const float* f2_l3b = (const float*)d_in[17];
    const float* f2_l4w = (const float*)d_in[18];
    const float* f2_l4b = (const float*)d_in[19];
    const float* f2_cw  = (const float*)d_in[20];
    const float* f2_cb  = (const float*)d_in[21];
    float* out = (float*)d_out;

    cudaFuncSetAttribute(deform_kernel, cudaFuncAttributeMaxDynamicSharedMemorySize,
                         TILE * HDIM * (int)sizeof(float));

    sf_kernel<<<dim3(4, 2), HDIM>>>(code, f1_cw, f1_cb, f2_cw, f2_cb);

    const int n_blocks = (4 * 4096) / TILE;  // 1024
    deform_kernel<<<n_blocks, NTHREADS, TILE * HDIM * sizeof(float)>>>(
        x, out,
        f1_l1w, f1_l1b, f1_l2w, f1_l2b, f1_l3w, f1_l3b, f1_l4w, f1_l4b,
        f2_l1w, f2_l1b, f2_l2w, f2_l2b, f2_l3w, f2_l3b, f2_l4w, f2_l4b);
}